// round 2
// baseline (speedup 1.0000x reference)
#include <cuda_runtime.h>
#include <math.h>

#define N2   8192
#define BHALF 4096
#define DDIM 128
#define BM   64
#define BN   64
#define CSPLIT 8
#define CHUNK (N2 / CSPLIT)    // 1024 columns per block
#define NTILES (CHUNK / BN)    // 16 column tiles per block
#define INV_TEMP 2.0f

__device__ float g_zn[N2 * DDIM];     // normalized rows (zi ++ zj)
__device__ float g_rowsum[N2];        // sum_j!=i exp(sim_ij / T)
__device__ float g_pos[N2];           // sim[i, i±B] / T

// ---------------------------------------------------------------------------
__global__ void zero_kernel(float* out) {
    int i = blockIdx.x * blockDim.x + threadIdx.x;
    if (i < N2) g_rowsum[i] = 0.0f;
    if (i == 0) out[0] = 0.0f;
}

// ---------------------------------------------------------------------------
// One block per row (8192 blocks, 128 threads). L2-normalize with eps clamp.
__global__ void normalize_kernel(const float* __restrict__ zi,
                                 const float* __restrict__ zj) {
    int row = blockIdx.x;
    const float* src = (row < BHALF) ? (zi + (size_t)row * DDIM)
                                     : (zj + (size_t)(row - BHALF) * DDIM);
    float v = src[threadIdx.x];
    float ss = v * v;
    #pragma unroll
    for (int o = 16; o; o >>= 1) ss += __shfl_xor_sync(0xffffffffu, ss, o);
    __shared__ float wss[4];
    if ((threadIdx.x & 31) == 0) wss[threadIdx.x >> 5] = ss;
    __syncthreads();
    float tot = wss[0] + wss[1] + wss[2] + wss[3];
    float norm = fmaxf(sqrtf(tot), 1e-8f);
    g_zn[(size_t)row * DDIM + threadIdx.x] = v / norm;
}

// ---------------------------------------------------------------------------
// Main kernel: block = (64-row tile) x (1024-column chunk).
// Shared tiles stored k-major: As[k][m], Bs[k][n]. 4x4 register tile/thread.
// Epilogue applies exp(2*sim) inline, skips the self column, captures pos.
__global__ void __launch_bounds__(256) simexp_kernel() {
    extern __shared__ float smem[];
    float (*As)[BM] = (float (*)[BM])smem;                 // [DDIM][BM]
    float (*Bs)[BN] = (float (*)[BN])(smem + DDIM * BM);   // [DDIM][BN]

    const int rowBase  = blockIdx.x * BM;
    const int colBase0 = blockIdx.y * CHUNK;
    const int tid = threadIdx.x;
    const int tx = tid & 15;     // column group (16)
    const int ty = tid >> 4;     // row group (16)

    // --- load A tile (64 rows x 128 k), transposed into smem ---
    {
        const int r  = tid & 63;
        const int kg = tid >> 6;                 // 0..3
        const float4* gsrc = (const float4*)(g_zn + (size_t)(rowBase + r) * DDIM);
        #pragma unroll
        for (int i = 0; i < 8; i++) {
            int k4 = kg + i * 4;
            float4 v = gsrc[k4];
            As[k4 * 4 + 0][r] = v.x;
            As[k4 * 4 + 1][r] = v.y;
            As[k4 * 4 + 2][r] = v.z;
            As[k4 * 4 + 3][r] = v.w;
        }
    }

    float rs[4] = {0.f, 0.f, 0.f, 0.f};
    const int gr0 = rowBase + ty * 4;

    for (int t = 0; t < NTILES; t++) {
        const int colBase = colBase0 + t * BN;
        __syncthreads();   // Bs reuse barrier (also covers initial As fill)
        {
            const int r  = tid & 63;
            const int kg = tid >> 6;
            const float4* gsrc = (const float4*)(g_zn + (size_t)(colBase + r) * DDIM);
            #pragma unroll
            for (int i = 0; i < 8; i++) {
                int k4 = kg + i * 4;
                float4 v = gsrc[k4];
                Bs[k4 * 4 + 0][r] = v.x;
                Bs[k4 * 4 + 1][r] = v.y;
                Bs[k4 * 4 + 2][r] = v.z;
                Bs[k4 * 4 + 3][r] = v.w;
            }
        }
        __syncthreads();

        float c[4][4] = {};
        #pragma unroll
        for (int k = 0; k < DDIM; k++) {
            float4 av = *(const float4*)&As[k][ty * 4];
            float4 bv = *(const float4*)&Bs[k][tx * 4];
            float a[4] = {av.x, av.y, av.z, av.w};
            float b[4] = {bv.x, bv.y, bv.z, bv.w};
            #pragma unroll
            for (int m = 0; m < 4; m++)
                #pragma unroll
                for (int n = 0; n < 4; n++)
                    c[m][n] = fmaf(a[m], b[n], c[m][n]);
        }

        // epilogue: exp + self-mask + positive capture
        #pragma unroll
        for (int m = 0; m < 4; m++) {
            const int gi   = gr0 + m;
            const int pcol = (gi < BHALF) ? (gi + BHALF) : (gi - BHALF);
            float acc = 0.0f;
            #pragma unroll
            for (int n = 0; n < 4; n++) {
                const int gj = colBase + tx * 4 + n;
                const float logit = c[m][n] * INV_TEMP;
                if (gj == pcol) g_pos[gi] = logit;   // unique writer
                if (gj != gi)  acc += __expf(logit); // mask self-diagonal
            }
            rs[m] += acc;
        }
    }

    // reduce partial row sums across the 16 tx lanes, then one atomic per row
    __syncthreads();
    float* rowacc = smem;   // reuse smem, 64 floats
    if (tid < BM) rowacc[tid] = 0.0f;
    __syncthreads();
    #pragma unroll
    for (int m = 0; m < 4; m++) atomicAdd(&rowacc[ty * 4 + m], rs[m]);
    __syncthreads();
    if (tid < BM) atomicAdd(&g_rowsum[rowBase + tid], rowacc[tid]);
}

// ---------------------------------------------------------------------------
__global__ void finalize_kernel(float* out) {
    int i = blockIdx.x * blockDim.x + threadIdx.x;
    float val = 0.0f;
    if (i < N2) val = logf(g_rowsum[i]) - g_pos[i];
    #pragma unroll
    for (int o = 16; o; o >>= 1) val += __shfl_xor_sync(0xffffffffu, val, o);
    __shared__ float ws[8];
    int lane = threadIdx.x & 31, w = threadIdx.x >> 5;
    if (lane == 0) ws[w] = val;
    __syncthreads();
    if (w == 0) {
        float v = (lane < 8) ? ws[lane] : 0.0f;
        #pragma unroll
        for (int o = 4; o; o >>= 1) v += __shfl_xor_sync(0xffffffffu, v, o);
        if (lane == 0) atomicAdd(out, v * (1.0f / N2));
    }
}

// ---------------------------------------------------------------------------
extern "C" void kernel_launch(void* const* d_in, const int* in_sizes, int n_in,
                              void* d_out, int out_size) {
    const float* zi = (const float*)d_in[0];
    const float* zj = (const float*)d_in[1];
    float* out = (float*)d_out;

    const int smem_bytes = 2 * DDIM * BM * (int)sizeof(float);  // 64 KB
    cudaFuncSetAttribute(simexp_kernel,
                         cudaFuncAttributeMaxDynamicSharedMemorySize, smem_bytes);

    zero_kernel<<<(N2 + 255) / 256, 256>>>(out);
    normalize_kernel<<<N2, DDIM>>>(zi, zj);
    simexp_kernel<<<dim3(N2 / BM, CSPLIT), 256, smem_bytes>>>();
    finalize_kernel<<<(N2 + 255) / 256, 256>>>(out);
}

// round 9
// speedup vs baseline: 8.3912x; 8.3912x over previous
#include <cuda_runtime.h>
#include <cuda_bf16.h>
#include <math.h>

#define N2    8192
#define BHALF 4096
#define DDIM  128
#define TM    128
#define TN    128
#define APAD  136              // padded row length (bf16) -> 272B stride, conflict-free ldmatrix
#define INV_TEMP 2.0f
#define K2EX  2.885390082f     // 2 * log2(e): exp(2x) = 2^(x*K2EX)

__device__ __nv_bfloat16 g_znb[N2 * DDIM];
__device__ float g_rowsum[N2];
__device__ float g_pos[N2];

__device__ __forceinline__ unsigned smem_u32(const void* p) {
    unsigned a;
    asm("{ .reg .u64 t; cvta.to.shared.u64 t, %1; cvt.u32.u64 %0, t; }"
        : "=r"(a) : "l"(p));
    return a;
}
__device__ __forceinline__ float ex2f(float x) {
    float r;
    asm("ex2.approx.f32 %0, %1;" : "=f"(r) : "f"(x));
    return r;
}
__device__ __forceinline__ void ldmatrix_x4(unsigned* r, unsigned addr) {
    asm volatile("ldmatrix.sync.aligned.m8n8.x4.shared.b16 {%0,%1,%2,%3}, [%4];"
                 : "=r"(r[0]), "=r"(r[1]), "=r"(r[2]), "=r"(r[3]) : "r"(addr));
}
__device__ __forceinline__ void ldmatrix_x2(unsigned* r, unsigned addr) {
    asm volatile("ldmatrix.sync.aligned.m8n8.x2.shared.b16 {%0,%1}, [%2];"
                 : "=r"(r[0]), "=r"(r[1]) : "r"(addr));
}
__device__ __forceinline__ void mma_bf16(float* c, const unsigned* a, const unsigned* b) {
    asm volatile(
        "mma.sync.aligned.m16n8k16.row.col.f32.bf16.bf16.f32 "
        "{%0,%1,%2,%3}, {%4,%5,%6,%7}, {%8,%9}, {%0,%1,%2,%3};"
        : "+f"(c[0]), "+f"(c[1]), "+f"(c[2]), "+f"(c[3])
        : "r"(a[0]), "r"(a[1]), "r"(a[2]), "r"(a[3]), "r"(b[0]), "r"(b[1]));
}

// ---------------------------------------------------------------------------
// One block per row. Also zeroes g_rowsum[row]; block 0 thread 0 zeroes out[0].
__global__ void normalize_kernel(const float* __restrict__ zi,
                                 const float* __restrict__ zj,
                                 float* out) {
    int row = blockIdx.x;
    if (threadIdx.x == 0) {
        g_rowsum[row] = 0.0f;
        if (row == 0) out[0] = 0.0f;
    }
    const float* src = (row < BHALF) ? (zi + (size_t)row * DDIM)
                                     : (zj + (size_t)(row - BHALF) * DDIM);
    float v = src[threadIdx.x];
    float ss = v * v;
    #pragma unroll
    for (int o = 16; o; o >>= 1) ss += __shfl_xor_sync(0xffffffffu, ss, o);
    __shared__ float wss[4];
    if ((threadIdx.x & 31) == 0) wss[threadIdx.x >> 5] = ss;
    __syncthreads();
    float norm = fmaxf(sqrtf(wss[0] + wss[1] + wss[2] + wss[3]), 1e-8f);
    g_znb[(size_t)row * DDIM + threadIdx.x] = __float2bfloat16(v / norm);
}

// ---------------------------------------------------------------------------
// CTA = 128x128 tile of sim = zn * zn^T. 8 warps, warp tile 32x64.
// A[M,K] and B[N,K] both row-major in smem; mma row.col consumes B via
// non-transposed ldmatrix (K contiguous).
__global__ void __launch_bounds__(256, 2) simexp_kernel() {
    extern __shared__ __nv_bfloat16 smem[];
    __nv_bfloat16* As = smem;                  // [128][APAD]
    __nv_bfloat16* Bs = smem + TM * APAD;      // [128][APAD]

    const int tid = threadIdx.x, wid = tid >> 5, lid = tid & 31;
    const int rowBase = blockIdx.x * TM;
    const int colBase = blockIdx.y * TN;
    const int warp_m = (wid & 3) * 32;         // 4 warps down
    const int warp_n = (wid >> 2) * 64;        // 2 warps across

    // tile intersects self-diagonal or positive diagonal?
    const bool special = (colBase == rowBase) ||
                         (colBase == rowBase + BHALF) ||
                         (colBase == rowBase - BHALF);

    // ---- load tiles: 128x128 bf16 each, 16B chunks, coalesced ----
    #pragma unroll
    for (int i = 0; i < 8; i++) {
        int ch = tid + i * 256;                 // 2048 chunks
        int r = ch >> 4, c = (ch & 15) * 8;
        *(uint4*)(As + r * APAD + c) =
            *(const uint4*)(g_znb + (size_t)(rowBase + r) * DDIM + c);
        *(uint4*)(Bs + r * APAD + c) =
            *(const uint4*)(g_znb + (size_t)(colBase + r) * DDIM + c);
    }
    __syncthreads();

    // ---- ldmatrix lane addressing ----
    const unsigned a_base = smem_u32(As +
        (warp_m + (lid & 15)) * APAD + (lid >> 4) * 8);
    const unsigned b_base = smem_u32(Bs +
        (warp_n + (lid & 7)) * APAD + ((lid >> 3) & 1) * 8);

    float acc[2][8][4] = {};

    #pragma unroll
    for (int ks = 0; ks < 8; ks++) {
        const unsigned koff = ks * 32;          // 16 bf16 = 32 bytes
        unsigned a0[4], a1[4];
        ldmatrix_x4(a0, a_base + koff);
        ldmatrix_x4(a1, a_base + koff + 16 * APAD * 2);
        #pragma unroll
        for (int nt = 0; nt < 8; nt++) {
            unsigned b[2];
            ldmatrix_x2(b, b_base + koff + nt * 8 * APAD * 2);
            mma_bf16(acc[0][nt], a0, b);
            mma_bf16(acc[1][nt], a1, b);
        }
    }

    // ---- epilogue: exp(2*sim), self-mask, positive capture, row sums ----
    const int g = lid >> 2, q = lid & 3;
    float rsum[2][2] = {};                      // [mt][row-low/row-high]

    if (!special) {
        #pragma unroll
        for (int mt = 0; mt < 2; mt++)
            #pragma unroll
            for (int nt = 0; nt < 8; nt++) {
                float* c = acc[mt][nt];
                rsum[mt][0] += ex2f(c[0] * K2EX) + ex2f(c[1] * K2EX);
                rsum[mt][1] += ex2f(c[2] * K2EX) + ex2f(c[3] * K2EX);
            }
    } else {
        #pragma unroll
        for (int mt = 0; mt < 2; mt++) {
            const int gi0 = rowBase + warp_m + mt * 16 + g;     // low row
            const int gi1 = gi0 + 8;                            // high row
            const int pc0 = (gi0 < BHALF) ? gi0 + BHALF : gi0 - BHALF;
            const int pc1 = (gi1 < BHALF) ? gi1 + BHALF : gi1 - BHALF;
            #pragma unroll
            for (int nt = 0; nt < 8; nt++) {
                float* c = acc[mt][nt];
                const int gj0 = colBase + warp_n + nt * 8 + q * 2;
                const int gj1 = gj0 + 1;
                if (gj0 == pc0) g_pos[gi0] = c[0] * INV_TEMP;
                if (gj1 == pc0) g_pos[gi0] = c[1] * INV_TEMP;
                if (gj0 == pc1) g_pos[gi1] = c[2] * INV_TEMP;
                if (gj1 == pc1) g_pos[gi1] = c[3] * INV_TEMP;
                if (gj0 != gi0) rsum[mt][0] += ex2f(c[0] * K2EX);
                if (gj1 != gi0) rsum[mt][0] += ex2f(c[1] * K2EX);
                if (gj0 != gi1) rsum[mt][1] += ex2f(c[2] * K2EX);
                if (gj1 != gi1) rsum[mt][1] += ex2f(c[3] * K2EX);
            }
        }
    }

    // reduce across the 4 lanes of each row group, one atomic per row frag
    #pragma unroll
    for (int mt = 0; mt < 2; mt++)
        #pragma unroll
        for (int h = 0; h < 2; h++) {
            float s = rsum[mt][h];
            s += __shfl_xor_sync(0xffffffffu, s, 1);
            s += __shfl_xor_sync(0xffffffffu, s, 2);
            if (q == 0)
                atomicAdd(&g_rowsum[rowBase + warp_m + mt * 16 + h * 8 + g], s);
        }
}

// ---------------------------------------------------------------------------
__global__ void finalize_kernel(float* out) {
    int i = blockIdx.x * blockDim.x + threadIdx.x;
    float val = 0.0f;
    if (i < N2) val = logf(g_rowsum[i]) - g_pos[i];
    #pragma unroll
    for (int o = 16; o; o >>= 1) val += __shfl_xor_sync(0xffffffffu, val, o);
    __shared__ float ws[8];
    int lane = threadIdx.x & 31, w = threadIdx.x >> 5;
    if (lane == 0) ws[w] = val;
    __syncthreads();
    if (w == 0) {
        float v = (lane < 8) ? ws[lane] : 0.0f;
        #pragma unroll
        for (int o = 4; o; o >>= 1) v += __shfl_xor_sync(0xffffffffu, v, o);
        if (lane == 0) atomicAdd(out, v * (1.0f / N2));
    }
}

// ---------------------------------------------------------------------------
extern "C" void kernel_launch(void* const* d_in, const int* in_sizes, int n_in,
                              void* d_out, int out_size) {
    const float* zi = (const float*)d_in[0];
    const float* zj = (const float*)d_in[1];
    float* out = (float*)d_out;

    const int smem_bytes = 2 * TM * APAD * (int)sizeof(__nv_bfloat16);  // 69632
    cudaFuncSetAttribute(simexp_kernel,
                         cudaFuncAttributeMaxDynamicSharedMemorySize, smem_bytes);

    normalize_kernel<<<N2, DDIM>>>(zi, zj, out);
    simexp_kernel<<<dim3(N2 / TM, N2 / TN), 256, smem_bytes>>>();
    finalize_kernel<<<(N2 + 255) / 256, 256>>>(out);
}

// round 10
// speedup vs baseline: 11.0208x; 1.3134x over previous
#include <cuda_runtime.h>
#include <cuda_bf16.h>
#include <math.h>

#define N2    8192
#define BHALF 4096
#define DDIM  128
#define TM    128
#define TN    128
#define NTB   64               // tile blocks per dim
#define NT_TRI (NTB * (NTB + 1) / 2)   // 2080 upper-triangle tiles
#define APAD  136              // padded row (bf16) -> 272B stride, conflict-free ldmatrix
#define INV_TEMP 2.0f
#define K2EX  2.885390082f     // 2*log2(e): exp(2x) = 2^(x*K2EX)

__device__ __nv_bfloat16 g_znb[N2 * DDIM];
__device__ float g_rowsum[N2];
__device__ float g_pos[N2];

__device__ __forceinline__ unsigned smem_u32(const void* p) {
    unsigned a;
    asm("{ .reg .u64 t; cvta.to.shared.u64 t, %1; cvt.u32.u64 %0, t; }"
        : "=r"(a) : "l"(p));
    return a;
}
__device__ __forceinline__ float ex2f(float x) {
    float r;
    asm("ex2.approx.f32 %0, %1;" : "=f"(r) : "f"(x));
    return r;
}
__device__ __forceinline__ void ldmatrix_x4(unsigned* r, unsigned addr) {
    asm volatile("ldmatrix.sync.aligned.m8n8.x4.shared.b16 {%0,%1,%2,%3}, [%4];"
                 : "=r"(r[0]), "=r"(r[1]), "=r"(r[2]), "=r"(r[3]) : "r"(addr));
}
__device__ __forceinline__ void ldmatrix_x2(unsigned* r, unsigned addr) {
    asm volatile("ldmatrix.sync.aligned.m8n8.x2.shared.b16 {%0,%1}, [%2];"
                 : "=r"(r[0]), "=r"(r[1]) : "r"(addr));
}
__device__ __forceinline__ void mma_bf16(float* c, const unsigned* a, const unsigned* b) {
    asm volatile(
        "mma.sync.aligned.m16n8k16.row.col.f32.bf16.bf16.f32 "
        "{%0,%1,%2,%3}, {%4,%5,%6,%7}, {%8,%9}, {%0,%1,%2,%3};"
        : "+f"(c[0]), "+f"(c[1]), "+f"(c[2]), "+f"(c[3])
        : "r"(a[0]), "r"(a[1]), "r"(a[2]), "r"(a[3]), "r"(b[0]), "r"(b[1]));
}

// ---------------------------------------------------------------------------
// Warp per row: float4 load, warp-shuffle reduce, packed bf16 store.
// Also zeroes g_rowsum[row]; row 0 lane 0 zeroes out[0].
__global__ void __launch_bounds__(256) normalize_kernel(const float* __restrict__ zi,
                                                        const float* __restrict__ zj,
                                                        float* out) {
    const int row  = blockIdx.x * 8 + (threadIdx.x >> 5);
    const int lane = threadIdx.x & 31;
    const float* src = (row < BHALF) ? (zi + (size_t)row * DDIM)
                                     : (zj + (size_t)(row - BHALF) * DDIM);
    float4 v = ((const float4*)src)[lane];
    float ss = v.x * v.x + v.y * v.y + v.z * v.z + v.w * v.w;
    #pragma unroll
    for (int o = 16; o; o >>= 1) ss += __shfl_xor_sync(0xffffffffu, ss, o);
    float inv = 1.0f / fmaxf(sqrtf(ss), 1e-8f);
    __nv_bfloat162 p0 = __float22bfloat162_rn(make_float2(v.x * inv, v.y * inv));
    __nv_bfloat162 p1 = __float22bfloat162_rn(make_float2(v.z * inv, v.w * inv));
    uint2 st;
    st.x = *(unsigned*)&p0;
    st.y = *(unsigned*)&p1;
    ((uint2*)(g_znb + (size_t)row * DDIM))[lane] = st;
    if (lane == 0) {
        g_rowsum[row] = 0.0f;
        if (row == 0) out[0] = 0.0f;
    }
}

// ---------------------------------------------------------------------------
// Upper-triangle tiles only (2080 CTAs). Off-diagonal tiles accumulate both
// row sums and (by symmetry) column sums. Diagonal tiles: rows only + self-mask.
// Pos-diagonal tiles (colBase == rowBase+BHALF): capture g_pos[i] and g_pos[i+B].
__global__ void __launch_bounds__(256, 2) simexp_kernel() {
    extern __shared__ __nv_bfloat16 smem[];
    __nv_bfloat16* As = smem;                  // [128][APAD]
    __nv_bfloat16* Bs = smem + TM * APAD;      // [128][APAD]

    // ---- triangular decode: idx -> (bi, bj), bj >= bi ----
    const int rem = NT_TRI - 1 - (int)blockIdx.x;
    int k = (int)((sqrtf(8.0f * (float)rem + 1.0f) - 1.0f) * 0.5f);
    while ((k + 1) * (k + 2) / 2 <= rem) k++;
    while (k * (k + 1) / 2 > rem) k--;
    const int bi = NTB - 1 - k;
    const int bj = NTB - 1 - (rem - k * (k + 1) / 2);

    const int tid = threadIdx.x, wid = tid >> 5, lid = tid & 31;
    const int rowBase = bi * TM;
    const int colBase = bj * TN;
    const int warp_m = (wid & 3) * 32;
    const int warp_n = (wid >> 2) * 64;

    const bool diag = (bi == bj);                       // self-diagonal tile
    const bool posT = (colBase == rowBase + BHALF);     // positive-diagonal tile

    // ---- load tiles ----
    #pragma unroll
    for (int i = 0; i < 8; i++) {
        int ch = tid + i * 256;
        int r = ch >> 4, c = (ch & 15) * 8;
        *(uint4*)(As + r * APAD + c) =
            *(const uint4*)(g_znb + (size_t)(rowBase + r) * DDIM + c);
        *(uint4*)(Bs + r * APAD + c) =
            *(const uint4*)(g_znb + (size_t)(colBase + r) * DDIM + c);
    }
    __syncthreads();

    const unsigned a_base = smem_u32(As +
        (warp_m + (lid & 15)) * APAD + (lid >> 4) * 8);
    const unsigned b_base = smem_u32(Bs +
        (warp_n + (lid & 7)) * APAD + ((lid >> 3) & 1) * 8);

    float acc[2][8][4] = {};

    #pragma unroll
    for (int ks = 0; ks < 8; ks++) {
        const unsigned koff = ks * 32;
        unsigned a0[4], a1[4];
        ldmatrix_x4(a0, a_base + koff);
        ldmatrix_x4(a1, a_base + koff + 16 * APAD * 2);
        #pragma unroll
        for (int nt = 0; nt < 8; nt++) {
            unsigned b[2];
            ldmatrix_x2(b, b_base + koff + nt * 8 * APAD * 2);
            mma_bf16(acc[0][nt], a0, b);
            mma_bf16(acc[1][nt], a1, b);
        }
    }

    // ---- epilogue ----
    const int g = lid >> 2, q = lid & 3;
    float rsum[2][2] = {};           // [mt][low/high 8-row half]
    float colp[8][2] = {};           // per-nt column partials (off-diag only)

    if (diag) {
        #pragma unroll
        for (int mt = 0; mt < 2; mt++) {
            const int li0 = warp_m + mt * 16 + g;       // local row (low)
            const int li1 = li0 + 8;                    // local row (high)
            #pragma unroll
            for (int nt = 0; nt < 8; nt++) {
                float* c = acc[mt][nt];
                const int lj0 = warp_n + nt * 8 + q * 2;
                const int lj1 = lj0 + 1;
                if (lj0 != li0) rsum[mt][0] += ex2f(c[0] * K2EX);
                if (lj1 != li0) rsum[mt][0] += ex2f(c[1] * K2EX);
                if (lj0 != li1) rsum[mt][1] += ex2f(c[2] * K2EX);
                if (lj1 != li1) rsum[mt][1] += ex2f(c[3] * K2EX);
            }
        }
    } else {
        if (posT) {
            // positives at local col == local row; sim symmetric so one value
            // serves g_pos[i] and g_pos[i+BHALF].
            #pragma unroll
            for (int mt = 0; mt < 2; mt++) {
                const int li0 = warp_m + mt * 16 + g;
                const int li1 = li0 + 8;
                #pragma unroll
                for (int nt = 0; nt < 8; nt++) {
                    float* c = acc[mt][nt];
                    const int lj0 = warp_n + nt * 8 + q * 2;
                    const int lj1 = lj0 + 1;
                    if (lj0 == li0) { float L = c[0] * INV_TEMP;
                        g_pos[rowBase + li0] = L; g_pos[colBase + lj0] = L; }
                    if (lj1 == li0) { float L = c[1] * INV_TEMP;
                        g_pos[rowBase + li0] = L; g_pos[colBase + lj1] = L; }
                    if (lj0 == li1) { float L = c[2] * INV_TEMP;
                        g_pos[rowBase + li1] = L; g_pos[colBase + lj0] = L; }
                    if (lj1 == li1) { float L = c[3] * INV_TEMP;
                        g_pos[rowBase + li1] = L; g_pos[colBase + lj1] = L; }
                }
            }
        }
        #pragma unroll
        for (int mt = 0; mt < 2; mt++)
            #pragma unroll
            for (int nt = 0; nt < 8; nt++) {
                float* c = acc[mt][nt];
                float e0 = ex2f(c[0] * K2EX), e1 = ex2f(c[1] * K2EX);
                float e2 = ex2f(c[2] * K2EX), e3 = ex2f(c[3] * K2EX);
                rsum[mt][0] += e0 + e1;
                rsum[mt][1] += e2 + e3;
                colp[nt][0] += e0 + e2;
                colp[nt][1] += e1 + e3;
            }
    }

    // row sums: reduce over q lanes, one atomic per row fragment
    #pragma unroll
    for (int mt = 0; mt < 2; mt++)
        #pragma unroll
        for (int h = 0; h < 2; h++) {
            float s = rsum[mt][h];
            s += __shfl_xor_sync(0xffffffffu, s, 1);
            s += __shfl_xor_sync(0xffffffffu, s, 2);
            if (q == 0)
                atomicAdd(&g_rowsum[rowBase + warp_m + mt * 16 + h * 8 + g], s);
        }

    // column sums (off-diagonal tiles): reduce over g lanes
    if (!diag) {
        #pragma unroll
        for (int nt = 0; nt < 8; nt++) {
            float s0 = colp[nt][0], s1 = colp[nt][1];
            #pragma unroll
            for (int o = 4; o <= 16; o <<= 1) {
                s0 += __shfl_xor_sync(0xffffffffu, s0, o);
                s1 += __shfl_xor_sync(0xffffffffu, s1, o);
            }
            if (g == 0) {
                const int cj = colBase + warp_n + nt * 8 + q * 2;
                atomicAdd(&g_rowsum[cj],     s0);
                atomicAdd(&g_rowsum[cj + 1], s1);
            }
        }
    }
}

// ---------------------------------------------------------------------------
__global__ void finalize_kernel(float* out) {
    int i = blockIdx.x * blockDim.x + threadIdx.x;
    float val = 0.0f;
    if (i < N2) val = logf(g_rowsum[i]) - g_pos[i];
    #pragma unroll
    for (int o = 16; o; o >>= 1) val += __shfl_xor_sync(0xffffffffu, val, o);
    __shared__ float ws[8];
    int lane = threadIdx.x & 31, w = threadIdx.x >> 5;
    if (lane == 0) ws[w] = val;
    __syncthreads();
    if (w == 0) {
        float v = (lane < 8) ? ws[lane] : 0.0f;
        #pragma unroll
        for (int o = 4; o; o >>= 1) v += __shfl_xor_sync(0xffffffffu, v, o);
        if (lane == 0) atomicAdd(out, v * (1.0f / N2));
    }
}

// ---------------------------------------------------------------------------
extern "C" void kernel_launch(void* const* d_in, const int* in_sizes, int n_in,
                              void* d_out, int out_size) {
    const float* zi = (const float*)d_in[0];
    const float* zj = (const float*)d_in[1];
    float* out = (float*)d_out;

    const int smem_bytes = 2 * TM * APAD * (int)sizeof(__nv_bfloat16);  // 69632
    cudaFuncSetAttribute(simexp_kernel,
                         cudaFuncAttributeMaxDynamicSharedMemorySize, smem_bytes);

    normalize_kernel<<<N2 / 8, 256>>>(zi, zj, out);
    simexp_kernel<<<NT_TRI, 256, smem_bytes>>>();
    finalize_kernel<<<(N2 + 255) / 256, 256>>>(out);
}